// round 3
// baseline (speedup 1.0000x reference)
#include <cuda_runtime.h>
#include <math.h>

// Fixed problem shape
#define BB 16
#define HH 544
#define WW 960
#define ROWS_TOTAL (BB * HH)            // 8704 image rows
#define NRPB 8                          // rows per block
#define GRID (ROWS_TOTAL / NRPB)        // 1088 blocks (exact)
#define THREADS 256
#define F4_PER_ROW (WW / 4)             // 240 float4 per row (< THREADS)
#define PAD_L 64                        // front zero pad (disp < 64)
#define PAD_R 8                         // back zero pad (x1i can reach W)
#define SSTRIDE (PAD_L + WW + PAD_R)    // 1032 floats per smem row

// Global accumulators: [0]=count, [1]=sum sl1(dl-dlgt)*m, [2]=sum sl1(recon-lgt)*m
__device__ double   g_acc[3];
__device__ unsigned g_done;

__device__ __forceinline__ float smooth_l1(float d) {
    float ad = fabsf(d);
    return (ad < 1.0f) ? 0.5f * ad * ad : ad - 0.5f;
}

__global__ void __launch_bounds__(THREADS)
fused_loss_kernel(const float* __restrict__ dl,
                  const float* __restrict__ seg,
                  const float* __restrict__ dlgt,
                  const float* __restrict__ lgt,
                  float* __restrict__ out)
{
    __shared__ float srow[NRPB][SSTRIDE];   // 33 KB

    const int tid  = threadIdx.x;
    const int row0 = blockIdx.x * NRPB;

    // ---- Zero the pads: warp r handles row r ----
    if (tid < NRPB * 32) {
        const int r  = tid >> 5;
        const int ln = tid & 31;
        srow[r][ln]      = 0.0f;
        srow[r][ln + 32] = 0.0f;
        if (ln < PAD_R) srow[r][PAD_L + WW + ln] = 0.0f;
    }

    // ---- Stage seg rows (coalesced float4, one column per thread) ----
    if (tid < F4_PER_ROW) {
        const float4* __restrict__ ps =
            reinterpret_cast<const float4*>(seg + (long)row0 * WW) + tid;
        #pragma unroll
        for (int r = 0; r < NRPB; r++) {
            *reinterpret_cast<float4*>(&srow[r][PAD_L + tid * 4]) = ps[r * F4_PER_ROW];
        }
    }
    __syncthreads();

    // ---- Main accumulation (branchless, no integer division) ----
    float cnt = 0.0f, sd = 0.0f, sr = 0.0f;

    if (tid < F4_PER_ROW) {
        const int  w   = tid * 4;
        const float wf = (float)w;
        const long base = (long)row0 * WW + w;
        const float4* __restrict__ pd = reinterpret_cast<const float4*>(dl   + base);
        const float4* __restrict__ pl = reinterpret_cast<const float4*>(lgt  + base);
        const float4* __restrict__ pg = reinterpret_cast<const float4*>(dlgt + base);

        #pragma unroll
        for (int r = 0; r < NRPB; r++) {
            const float4 dv = pd[r * F4_PER_ROW];
            const float4 lv = pl[r * F4_PER_ROW];
            const float4 gv = pg[r * F4_PER_ROW];
            const float* __restrict__ s = &srow[r][PAD_L];

            #pragma unroll
            for (int k = 0; k < 4; k++) {
                const float d  = (&dv.x)[k];
                const float l  = (&lv.x)[k];
                const float dg = (&gv.x)[k];
                const bool  msk = (l > 0.0f);

                // disparity term
                const float t0 = smooth_l1(d - dg);

                // horizontal bilinear warp with implicit zero padding:
                // d in [0,64) -> 64 + x0i in [0, 1023]; x1i index <= 1024 (padded)
                const float sx  = (wf + (float)k) - d;
                const float x0f = floorf(sx);
                const float wx  = sx - x0f;
                const int   x0i = (int)x0f;
                const float g0  = s[x0i];
                const float g1  = s[x0i + 1];
                const float warped = g0 + wx * (g1 - g0);

                const float recon = 1.0f / (1.0f + __expf(-warped));
                const float t1 = smooth_l1(recon - l);

                cnt += msk ? 1.0f : 0.0f;
                sd  += msk ? t0   : 0.0f;
                sr  += msk ? t1   : 0.0f;
            }
        }
    }

    // ---- Block reduction: warp shuffles -> shared -> fp64 atomics ----
    #pragma unroll
    for (int off = 16; off > 0; off >>= 1) {
        cnt += __shfl_down_sync(0xffffffffu, cnt, off);
        sd  += __shfl_down_sync(0xffffffffu, sd,  off);
        sr  += __shfl_down_sync(0xffffffffu, sr,  off);
    }

    __shared__ float s_cnt[THREADS / 32];
    __shared__ float s_sd [THREADS / 32];
    __shared__ float s_sr [THREADS / 32];

    const int lane = tid & 31;
    const int wid  = tid >> 5;
    if (lane == 0) { s_cnt[wid] = cnt; s_sd[wid] = sd; s_sr[wid] = sr; }
    __syncthreads();

    if (wid == 0) {
        cnt = (lane < THREADS / 32) ? s_cnt[lane] : 0.0f;
        sd  = (lane < THREADS / 32) ? s_sd [lane] : 0.0f;
        sr  = (lane < THREADS / 32) ? s_sr [lane] : 0.0f;
        #pragma unroll
        for (int off = 4; off > 0; off >>= 1) {
            cnt += __shfl_down_sync(0xffffffffu, cnt, off);
            sd  += __shfl_down_sync(0xffffffffu, sd,  off);
            sr  += __shfl_down_sync(0xffffffffu, sr,  off);
        }
        if (lane == 0) {
            atomicAdd(&g_acc[0], (double)cnt);
            atomicAdd(&g_acc[1], (double)sd);
            atomicAdd(&g_acc[2], (double)sr);

            // ---- Last-block finalize (fused) ----
            __threadfence();
            const unsigned ticket = atomicAdd(&g_done, 1u);
            if (ticket == GRID - 1) {
                const double tc = g_acc[0];
                const double ts = g_acc[1];
                const double tr = g_acc[2];

                float loss = (float)(ts / tc);
                if (isnan(loss)) loss = 0.0f;
                const float loss_recon = (float)(tr / tc);
                out[0] = loss + 0.5f * loss_recon;

                // Reset state for the next (graph-replayed) call
                g_acc[0] = 0.0;
                g_acc[1] = 0.0;
                g_acc[2] = 0.0;
                g_done   = 0u;
            }
        }
    }
}

extern "C" void kernel_launch(void* const* d_in, const int* in_sizes, int n_in,
                              void* d_out, int out_size)
{
    const float* dl   = (const float*)d_in[0];
    const float* seg  = (const float*)d_in[1];
    const float* dlgt = (const float*)d_in[2];
    const float* lgt  = (const float*)d_in[3];
    float* out = (float*)d_out;

    fused_loss_kernel<<<GRID, THREADS>>>(dl, seg, dlgt, lgt, out);
}

// round 4
// speedup vs baseline: 1.1002x; 1.1002x over previous
#include <cuda_runtime.h>
#include <math.h>

// Fixed problem shape
#define BB 16
#define HH 544
#define WW 960
#define ROWS_TOTAL (BB * HH)            // 8704 image rows
#define NRPB 4                          // rows per block
#define GRID (ROWS_TOTAL / NRPB)        // 2176 blocks (exact)
#define THREADS 256
#define F4_PER_ROW (WW / 4)             // 240 float4 per row
#define WORK (NRPB * F4_PER_ROW)        // 960 float4 work items per block
#define NITER 4                         // ceil(960/256); last iter partial (tid<192)
#define PAD_L 64                        // front zero pad (disp < 64)
#define PAD_R 8                         // back zero pad (x1i can reach W)
#define SSTRIDE (PAD_L + WW + PAD_R)    // 1032 floats per padded smem row

// Global accumulators: [0]=count, [1]=sum sl1(dl-dlgt)*m, [2]=sum sl1(recon-lgt)*m
__device__ double   g_acc[3];
__device__ unsigned g_done;

__device__ __forceinline__ float smooth_l1(float d) {
    float ad = fabsf(d);
    return (ad < 1.0f) ? 0.5f * ad * ad : ad - 0.5f;
}

__global__ void __launch_bounds__(THREADS)
fused_loss_kernel(const float* __restrict__ dl,
                  const float* __restrict__ seg,
                  const float* __restrict__ dlgt,
                  const float* __restrict__ lgt,
                  float* __restrict__ out)
{
    __shared__ float srow[NRPB][SSTRIDE];   // 16.5 KB

    const int tid  = threadIdx.x;
    const int row0 = blockIdx.x * NRPB;
    const long gbase = (long)row0 * WW;

    // ---- Zero pads: front 4*64 = 256 floats (one per thread), back 4*8 = 32 ----
    srow[tid >> 6][tid & 63] = 0.0f;
    if (tid < NRPB * PAD_R) srow[tid >> 3][PAD_L + WW + (tid & 7)] = 0.0f;

    // ---- Per-thread work-item decode (r, c) + front-batched global loads ----
    int   rr[NITER], cc[NITER];
    bool  act[NITER];
    float4 sv[NITER], dv[NITER], lv[NITER], gv[NITER];

    #pragma unroll
    for (int j = 0; j < NITER; j++) {
        const int i = tid + j * THREADS;
        act[j] = (i < WORK);
        const int r = i / F4_PER_ROW;          // mul-hi/shift
        const int c = i - r * F4_PER_ROW;
        rr[j] = r; cc[j] = c;
        if (act[j]) {
            const long idx = gbase + (long)r * WW + c * 4;
            sv[j] = *reinterpret_cast<const float4*>(seg  + idx);
            dv[j] = *reinterpret_cast<const float4*>(dl   + idx);
            lv[j] = *reinterpret_cast<const float4*>(lgt  + idx);
            gv[j] = *reinterpret_cast<const float4*>(dlgt + idx);
        }
    }

    // ---- Stage seg into padded smem ----
    #pragma unroll
    for (int j = 0; j < NITER; j++) {
        if (act[j]) {
            *reinterpret_cast<float4*>(&srow[rr[j]][PAD_L + cc[j] * 4]) = sv[j];
        }
    }
    __syncthreads();

    // ---- Main accumulation (branchless, padded gathers) ----
    float cnt = 0.0f, sd = 0.0f, sr = 0.0f;

    #pragma unroll
    for (int j = 0; j < NITER; j++) {
        if (!act[j]) continue;
        const float wf = (float)(cc[j] * 4);
        const float* __restrict__ s = &srow[rr[j]][PAD_L];

        #pragma unroll
        for (int k = 0; k < 4; k++) {
            const float d  = (&dv[j].x)[k];
            const float l  = (&lv[j].x)[k];
            const float dg = (&gv[j].x)[k];
            const bool  msk = (l > 0.0f);

            const float t0 = smooth_l1(d - dg);

            // horizontal bilinear warp; d in [0,64) keeps 64+x0i in [0,1023],
            // pads reproduce zeros-padding semantics exactly
            const float sx  = (wf + (float)k) - d;
            const float x0f = floorf(sx);
            const float wx  = sx - x0f;
            const int   x0i = (int)x0f;
            const float g0  = s[x0i];
            const float g1  = s[x0i + 1];
            const float warped = g0 + wx * (g1 - g0);

            const float recon = 1.0f / (1.0f + __expf(-warped));
            const float t1 = smooth_l1(recon - l);

            cnt += msk ? 1.0f : 0.0f;
            sd  += msk ? t0   : 0.0f;
            sr  += msk ? t1   : 0.0f;
        }
    }

    // ---- Block reduction: warp shuffles -> shared -> fp64 atomics ----
    #pragma unroll
    for (int off = 16; off > 0; off >>= 1) {
        cnt += __shfl_down_sync(0xffffffffu, cnt, off);
        sd  += __shfl_down_sync(0xffffffffu, sd,  off);
        sr  += __shfl_down_sync(0xffffffffu, sr,  off);
    }

    __shared__ float s_cnt[THREADS / 32];
    __shared__ float s_sd [THREADS / 32];
    __shared__ float s_sr [THREADS / 32];

    const int lane = tid & 31;
    const int wid  = tid >> 5;
    if (lane == 0) { s_cnt[wid] = cnt; s_sd[wid] = sd; s_sr[wid] = sr; }
    __syncthreads();

    if (wid == 0) {
        cnt = (lane < THREADS / 32) ? s_cnt[lane] : 0.0f;
        sd  = (lane < THREADS / 32) ? s_sd [lane] : 0.0f;
        sr  = (lane < THREADS / 32) ? s_sr [lane] : 0.0f;
        #pragma unroll
        for (int off = 4; off > 0; off >>= 1) {
            cnt += __shfl_down_sync(0xffffffffu, cnt, off);
            sd  += __shfl_down_sync(0xffffffffu, sd,  off);
            sr  += __shfl_down_sync(0xffffffffu, sr,  off);
        }
        if (lane == 0) {
            atomicAdd(&g_acc[0], (double)cnt);
            atomicAdd(&g_acc[1], (double)sd);
            atomicAdd(&g_acc[2], (double)sr);

            // ---- Last-block finalize (fused) ----
            __threadfence();
            const unsigned ticket = atomicAdd(&g_done, 1u);
            if (ticket == GRID - 1) {
                const double tc = g_acc[0];
                const double ts = g_acc[1];
                const double tr = g_acc[2];

                float loss = (float)(ts / tc);
                if (isnan(loss)) loss = 0.0f;
                const float loss_recon = (float)(tr / tc);
                out[0] = loss + 0.5f * loss_recon;

                g_acc[0] = 0.0;
                g_acc[1] = 0.0;
                g_acc[2] = 0.0;
                g_done   = 0u;
            }
        }
    }
}

extern "C" void kernel_launch(void* const* d_in, const int* in_sizes, int n_in,
                              void* d_out, int out_size)
{
    const float* dl   = (const float*)d_in[0];
    const float* seg  = (const float*)d_in[1];
    const float* dlgt = (const float*)d_in[2];
    const float* lgt  = (const float*)d_in[3];
    float* out = (float*)d_out;

    fused_loss_kernel<<<GRID, THREADS>>>(dl, seg, dlgt, lgt, out);
}